// round 11
// baseline (speedup 1.0000x reference)
#include <cuda_runtime.h>
#include <cuda_bf16.h>
#include <cstdint>

// ---------------------------------------------------------------------------
// ASDHead v8 — fragment-major B + fused output:
//  k_frag  : W_proj -> per-lane mma fragment u64s (hi/lo, W_f and W_s).
//            Kills the 8-way LDS bank conflict that dominated v7's GEMM
//            (BPAD=72: row-group stride 288 words = 0 mod 32).
//  k_sgemm : s_proj = slots @ W_s + b_proj via HMMA core (grid 16).
//  k_main  : f_proj GEMM (HMMA, frags via direct L1-resident LDG.64) fused
//            with relu-dot epilogue (grid 256). No f_proj gmem round-trip.
// ---------------------------------------------------------------------------

#define D_MODEL 256
#define D_HID   128
#define BATCH   8
#define SEQ     1024
#define NSLOT   64
#define MROWS   (BATCH * SEQ)
#define NFRAG   8192     // 4 kc * 4 ks * 16 ng * 32 lanes

typedef unsigned long long u64;
typedef unsigned int u32;

__device__ float g_sproj[BATCH * NSLOT * D_HID];   // 256 KB
__device__ u64 g_BfHi[NFRAG], g_BfLo[NFRAG];       // W_f frags, 64 KB each
__device__ u64 g_BsHi[NFRAG], g_BsLo[NFRAG];       // W_s frags

// -------------------- helpers ----------------------------------------------
__device__ __forceinline__ u64 fma2(u64 a, u64 b, u64 c) {
    u64 d; asm("fma.rn.f32x2 %0, %1, %2, %3;" : "=l"(d) : "l"(a), "l"(b), "l"(c));
    return d;
}
__device__ __forceinline__ u64 add2(u64 a, u64 b) {
    u64 d; asm("add.rn.f32x2 %0, %1, %2;" : "=l"(d) : "l"(a), "l"(b));
    return d;
}
__device__ __forceinline__ void unpack2(u64 v, float& lo, float& hi) {
    asm("mov.b64 {%0, %1}, %2;" : "=f"(lo), "=f"(hi) : "l"(v));
}
__device__ __forceinline__ u64 relu2(u64 x) {
    float lo, hi; unpack2(x, lo, hi);
    lo = fmaxf(lo, 0.f); hi = fmaxf(hi, 0.f);
    u64 r; asm("mov.b64 %0, {%1, %2};" : "=l"(r) : "f"(lo), "f"(hi));
    return r;
}
// packed bf16x2: low half = a, high half = b (validated in v6.1, rel 3.9e-6)
__device__ __forceinline__ u32 cvt_bf16x2(float a, float b) {
    u32 r; asm("cvt.rn.bf16x2.f32 %0, %1, %2;" : "=r"(r) : "f"(b), "f"(a));
    return r;
}
__device__ __forceinline__ void split2(float x, float y, u32& hi, u32& lo) {
    hi = cvt_bf16x2(x, y);
    float hx = __uint_as_float(hi << 16);
    float hy = __uint_as_float(hi & 0xFFFF0000u);
    lo = cvt_bf16x2(x - hx, y - hy);
}
__device__ __forceinline__ void mma16816(float& c0, float& c1, float& c2, float& c3,
                                         u32 a0, u32 a1, u32 a2, u32 a3,
                                         u32 b0, u32 b1) {
    asm volatile(
        "mma.sync.aligned.m16n8k16.row.col.f32.bf16.bf16.f32 "
        "{%0,%1,%2,%3}, {%4,%5,%6,%7}, {%8,%9}, {%0,%1,%2,%3};"
        : "+f"(c0), "+f"(c1), "+f"(c2), "+f"(c3)
        : "r"(a0), "r"(a1), "r"(a2), "r"(a3), "r"(b0), "r"(b1));
}

// -------------------- K_frag: W_proj -> fragment-major B --------------------
// grid 64 x 256 = 16384 threads = 2 (f/s) x 8192 entries.
// Entry (kc,ks,ng,lane) = u64{ b1=W[k+8..9][n], b0=W[k..k+1][n] } for
// k = kc*64 + ks*16 + (lane&3)*2, n = ng*8 + (lane>>2).
__global__ void __launch_bounds__(256) k_frag(const float* __restrict__ Wproj) {
    int e = blockIdx.x * 256 + threadIdx.x;
    int slot = e >> 13;              // 0 = W_f, 1 = W_s
    int r = e & (NFRAG - 1);
    int lane = r & 31, ng = (r >> 5) & 15, ks = (r >> 9) & 3, kc = r >> 11;
    int krow = slot * 256 + kc * 64 + ks * 16 + (lane & 3) * 2;
    int n = ng * 8 + (lane >> 2);
    const float* W = Wproj + n;
    float x0 = W[(size_t)krow * D_HID];
    float x1 = W[(size_t)(krow + 1) * D_HID];
    float x8 = W[(size_t)(krow + 8) * D_HID];
    float x9 = W[(size_t)(krow + 9) * D_HID];
    u32 h0, l0, h1, l1;
    split2(x0, x1, h0, l0);
    split2(x8, x9, h1, l1);
    u64 hv = (u64)h0 | ((u64)h1 << 32);
    u64 lv = (u64)l0 | ((u64)l1 << 32);
    if (slot == 0) { g_BfHi[r] = hv; g_BfLo[r] = lv; }
    else           { g_BsHi[r] = hv; g_BsLo[r] = lv; }
}

// -------------------- HMMA core --------------------------------------------
// One warp: rows mbase..mbase+15 (block-local), cols n0..n0+31.
// acc[j][0..3]: j-th 8-col group. A frags direct LDG; B frags direct LDG.64.
__device__ __forceinline__ void gemm_core(const float* __restrict__ arow,
                                          const u64* __restrict__ BH,
                                          const u64* __restrict__ BL,
                                          int ngbase, int lane,
                                          float acc[4][4]) {
#pragma unroll 1
    for (int kc = 0; kc < 4; kc++) {
#pragma unroll
        for (int ks = 0; ks < 4; ks++) {
            int kk = kc * 64 + ks * 16;
            float2 p00 = *(const float2*)(arow + kk);
            float2 p10 = *(const float2*)(arow + kk + 8 * D_MODEL);
            float2 p01 = *(const float2*)(arow + kk + 8);
            float2 p11 = *(const float2*)(arow + kk + 8 * D_MODEL + 8);
            u32 ah[4], al[4];
            split2(p00.x, p00.y, ah[0], al[0]);
            split2(p10.x, p10.y, ah[1], al[1]);
            split2(p01.x, p01.y, ah[2], al[2]);
            split2(p11.x, p11.y, ah[3], al[3]);

            int base = ((kc * 4 + ks) * 16 + ngbase) * 32 + lane;
#pragma unroll
            for (int j = 0; j < 4; j++) {
                u64 fh = BH[base + j * 32];
                u64 fl = BL[base + j * 32];
                u32 bh0 = (u32)fh, bh1 = (u32)(fh >> 32);
                u32 bl0 = (u32)fl, bl1 = (u32)(fl >> 32);
                mma16816(acc[j][0], acc[j][1], acc[j][2], acc[j][3],
                         ah[0], ah[1], ah[2], ah[3], bh0, bh1);
                mma16816(acc[j][0], acc[j][1], acc[j][2], acc[j][3],
                         ah[0], ah[1], ah[2], ah[3], bl0, bl1);
                mma16816(acc[j][0], acc[j][1], acc[j][2], acc[j][3],
                         al[0], al[1], al[2], al[3], bh0, bh1);
            }
        }
    }
}

// -------------------- K_sgemm: s_proj ---------------------------------------
// grid 16: m0 = blk*32 over 512 slot rows.
__global__ void __launch_bounds__(256) k_sgemm(const float* __restrict__ slots,
                                               const float* __restrict__ bproj) {
    int tid = threadIdx.x, wid = tid >> 5, lane = tid & 31;
    int m0 = blockIdx.x * 32;
    int mbase = (wid & 1) * 16, n0 = (wid >> 1) * 32;
    const float* arow = slots + (size_t)(m0 + mbase + (lane >> 2)) * D_MODEL
                              + (lane & 3) * 2;
    float acc[4][4];
#pragma unroll
    for (int j = 0; j < 4; j++)
#pragma unroll
        for (int q = 0; q < 4; q++) acc[j][q] = 0.f;

    gemm_core(arow, g_BsHi, g_BsLo, (wid >> 1) * 4, lane, acc);

    int r0 = m0 + mbase + (lane >> 2);
#pragma unroll
    for (int j = 0; j < 4; j++) {
        int col = n0 + j * 8 + (lane & 3) * 2;
        float2 bp = *(const float2*)(bproj + col);
        float2 v0; v0.x = acc[j][0] + bp.x; v0.y = acc[j][1] + bp.y;
        float2 v1; v1.x = acc[j][2] + bp.x; v1.y = acc[j][3] + bp.y;
        *(float2*)(g_sproj + (size_t)r0 * D_HID + col) = v0;
        *(float2*)(g_sproj + (size_t)(r0 + 8) * D_HID + col) = v1;
    }
}

// -------------------- K_main: fused GEMM + relu-dot -------------------------
// grid 256: b = blk>>5, t0 = (blk&31)*32.
// Phase A: 32x128 f-tile via gemm_core -> fsh.  Phase B: 4t x 2n relu-dot.
#define FS 132
#define MAIN_SMEM ((32 * FS + 64 * FS + 128) * 4)   // 51200 B

__global__ void __launch_bounds__(256) k_main(const float* __restrict__ features,
                                              const float* __restrict__ whead,
                                              const float* __restrict__ bhead,
                                              float* __restrict__ out) {
    extern __shared__ float sm[];
    float* fsh = sm;                    // 32 x 132
    float* ssh = sm + 32 * FS;          // 64 x 132
    u64*   wsh = (u64*)(sm + 32 * FS + 64 * FS);

    int tid = threadIdx.x, wid = tid >> 5, lane = tid & 31;
    int b = blockIdx.x >> 5, t0 = (blockIdx.x & 31) * 32;
    int mbase = (wid & 1) * 16, n0 = (wid >> 1) * 32;

    // stage s/w early — LDG latency hides under Phase A
#pragma unroll
    for (int i = 0; i < 8; i++) {
        int q = i * 256 + tid;
        int r = q >> 5, c4 = (q & 31) * 4;
        *(float4*)&ssh[r * FS + c4] =
            *(const float4*)(g_sproj + (size_t)(b * NSLOT + r) * D_HID + c4);
    }
    if (tid < 64) wsh[tid] = ((const u64*)whead)[tid];
    float bh = bhead[0];

    // ---------------- Phase A: HMMA GEMM --------------------------------
    const float* arow = features
        + (size_t)(b * SEQ + t0 + mbase + (lane >> 2)) * D_MODEL + (lane & 3) * 2;
    float acc[4][4];
#pragma unroll
    for (int j = 0; j < 4; j++)
#pragma unroll
        for (int q = 0; q < 4; q++) acc[j][q] = 0.f;

    gemm_core(arow, g_BfHi, g_BfLo, (wid >> 1) * 4, lane, acc);

    // acc -> fsh (block-local rows; STS.64, ~2-way worst case)
    int mrow = mbase + (lane >> 2);
#pragma unroll
    for (int j = 0; j < 4; j++) {
        int col = n0 + j * 8 + (lane & 3) * 2;
        float2 v0; v0.x = acc[j][0]; v0.y = acc[j][1];
        float2 v1; v1.x = acc[j][2]; v1.y = acc[j][3];
        *(float2*)&fsh[mrow * FS + col] = v0;
        *(float2*)&fsh[(mrow + 8) * FS + col] = v1;
    }
    __syncthreads();

    // ---------------- Phase B: relu-dot, 4t x 2n ------------------------
    int tq = lane >> 2, np = lane & 3;
    int nn = wid * 8 + np * 2;
    const float* fp = fsh + tq * FS;
    const float* sp = ssh + nn * FS;

    u64 bacc[4][2];
#pragma unroll
    for (int i = 0; i < 4; i++) { bacc[i][0] = 0ULL; bacc[i][1] = 0ULL; }

#pragma unroll 4
    for (int hp = 0; hp < 64; hp++) {
        u64 w2 = wsh[hp];
        u64 s20 = *(const u64*)&sp[2 * hp];
        u64 s21 = *(const u64*)&sp[FS + 2 * hp];
#pragma unroll
        for (int i = 0; i < 4; i++) {
            u64 f2 = *(const u64*)&fp[i * 8 * FS + 2 * hp];
            bacc[i][0] = fma2(relu2(add2(f2, s20)), w2, bacc[i][0]);
            bacc[i][1] = fma2(relu2(add2(f2, s21)), w2, bacc[i][1]);
        }
    }

#pragma unroll
    for (int i = 0; i < 4; i++) {
        int t = tq + 8 * i;
        float a, c, d, e;
        unpack2(bacc[i][0], a, c);
        unpack2(bacc[i][1], d, e);
        float2 o; o.x = a + c + bh; o.y = d + e + bh;
        *(float2*)&out[(size_t)(b * SEQ + t0 + t) * NSLOT + nn] = o;
    }
}

// -------------------- launch -----------------------------------------------
extern "C" void kernel_launch(void* const* d_in, const int* in_sizes, int n_in,
                              void* d_out, int out_size) {
    const float* features = (const float*)d_in[0];
    const float* slots    = (const float*)d_in[1];
    const float* W_proj   = (const float*)d_in[2];
    const float* b_proj   = (const float*)d_in[3];
    const float* w_head   = (const float*)d_in[4];
    const float* b_head   = (const float*)d_in[5];
    float* out = (float*)d_out;

    cudaFuncSetAttribute(k_main, cudaFuncAttributeMaxDynamicSharedMemorySize,
                         MAIN_SMEM);

    k_frag<<<64, 256>>>(W_proj);
    k_sgemm<<<16, 256>>>(slots, b_proj);
    k_main<<<256, 256, MAIN_SMEM>>>(features, w_head, b_head, out);
}

// round 13
// speedup vs baseline: 1.1634x; 1.1634x over previous
#include <cuda_runtime.h>
#include <cuda_bf16.h>
#include <cstdint>

// ---------------------------------------------------------------------------
// ASDHead v9 — two kernels, v7-proven HMMA core, fused epilogue:
//  k_sgemm : s_proj = slots @ W_s + b_proj.  B staged straight from fp32
//            W_proj (transpose-in-registers), v7 smem-frag mainloop. grid 16.
//  k_main  : f_proj GEMM (same core/staging) fused with relu-dot epilogue.
//            fsh aliases dead B tile; 71KB smem, 2 blocks/SM, grid 256.
// R11 lesson: v7's smem frag reads were conflict-free all along (bank =
// 4*(lane>>2)+(lane&3)); v8's gmem-frag rewrite was the regression. Revert
// mechanism, keep fusion, delete the two ~4us helper launches.
// ---------------------------------------------------------------------------

#define D_MODEL 256
#define D_HID   128
#define BATCH   8
#define SEQ     1024
#define NSLOT   64
#define MROWS   (BATCH * SEQ)
#define BPAD    72

typedef unsigned long long u64;
typedef unsigned int u32;

__device__ float g_sproj[BATCH * NSLOT * D_HID];   // 256 KB

// -------------------- helpers ----------------------------------------------
__device__ __forceinline__ u64 fma2(u64 a, u64 b, u64 c) {
    u64 d; asm("fma.rn.f32x2 %0, %1, %2, %3;" : "=l"(d) : "l"(a), "l"(b), "l"(c));
    return d;
}
__device__ __forceinline__ u64 add2(u64 a, u64 b) {
    u64 d; asm("add.rn.f32x2 %0, %1, %2;" : "=l"(d) : "l"(a), "l"(b));
    return d;
}
__device__ __forceinline__ void unpack2(u64 v, float& lo, float& hi) {
    asm("mov.b64 {%0, %1}, %2;" : "=f"(lo), "=f"(hi) : "l"(v));
}
__device__ __forceinline__ u64 relu2(u64 x) {
    float lo, hi; unpack2(x, lo, hi);
    lo = fmaxf(lo, 0.f); hi = fmaxf(hi, 0.f);
    u64 r; asm("mov.b64 %0, {%1, %2};" : "=l"(r) : "f"(lo), "f"(hi));
    return r;
}
__device__ __forceinline__ u32 cvt_bf16x2(float a, float b) {
    u32 r; asm("cvt.rn.bf16x2.f32 %0, %1, %2;" : "=r"(r) : "f"(b), "f"(a));
    return r;
}
__device__ __forceinline__ void split2(float x, float y, u32& hi, u32& lo) {
    hi = cvt_bf16x2(x, y);
    float hx = __uint_as_float(hi << 16);
    float hy = __uint_as_float(hi & 0xFFFF0000u);
    lo = cvt_bf16x2(x - hx, y - hy);
}
__device__ __forceinline__ void mma16816(float& c0, float& c1, float& c2, float& c3,
                                         u32 a0, u32 a1, u32 a2, u32 a3,
                                         u32 b0, u32 b1) {
    asm volatile(
        "mma.sync.aligned.m16n8k16.row.col.f32.bf16.bf16.f32 "
        "{%0,%1,%2,%3}, {%4,%5,%6,%7}, {%8,%9}, {%0,%1,%2,%3};"
        : "+f"(c0), "+f"(c1), "+f"(c2), "+f"(c3)
        : "r"(a0), "r"(a1), "r"(a2), "r"(a3), "r"(b0), "r"(b1));
}

// ---- stage one 128h x 64k B chunk from fp32 W_proj into bf16 hi/lo smem ----
// thread: h = tid&127, kg = tid>>7 (32 k each). Warp LDG.32 = 128B coalesced.
__device__ __forceinline__ void stage_B(const float* __restrict__ Wproj,
                                        int koff, int kc, int tid,
                                        __nv_bfloat16* Bhi, __nv_bfloat16* Blo) {
    int h = tid & 127, kg = tid >> 7;
    const float* wp = Wproj + (size_t)(koff + kc * 64 + kg * 32) * D_HID + h;
#pragma unroll
    for (int grp = 0; grp < 4; grp++) {
        u32 hb[4], lb[4];
#pragma unroll
        for (int p = 0; p < 4; p++) {
            float x0 = wp[(grp * 8 + 2 * p) * D_HID];
            float x1 = wp[(grp * 8 + 2 * p + 1) * D_HID];
            split2(x0, x1, hb[p], lb[p]);
        }
        *(uint4*)(Bhi + h * BPAD + kg * 32 + grp * 8) =
            make_uint4(hb[0], hb[1], hb[2], hb[3]);
        *(uint4*)(Blo + h * BPAD + kg * 32 + grp * 8) =
            make_uint4(lb[0], lb[1], lb[2], lb[3]);
    }
}

// ---- v7 HMMA mainloop body for one 16-k step (A direct LDG + smem B) ------
__device__ __forceinline__ void mma_step(const float* __restrict__ arow, int kk,
                                         const __nv_bfloat16* Bhi,
                                         const __nv_bfloat16* Blo,
                                         int n0, int lane, float acc[4][4]) {
    float2 p00 = *(const float2*)(arow + kk);
    float2 p10 = *(const float2*)(arow + kk + 8 * D_MODEL);
    float2 p01 = *(const float2*)(arow + kk + 8);
    float2 p11 = *(const float2*)(arow + kk + 8 * D_MODEL + 8);
    u32 ah[4], al[4];
    split2(p00.x, p00.y, ah[0], al[0]);
    split2(p10.x, p10.y, ah[1], al[1]);
    split2(p01.x, p01.y, ah[2], al[2]);
    split2(p11.x, p11.y, ah[3], al[3]);
    int kb = (kk & 63) + (lane & 3) * 2;         // offset within 64-k chunk
#pragma unroll
    for (int j = 0; j < 4; j++) {
        int nrow = n0 + j * 8 + (lane >> 2);
        u32 bh0 = *(const u32*)(Bhi + nrow * BPAD + kb);
        u32 bh1 = *(const u32*)(Bhi + nrow * BPAD + kb + 8);
        u32 bl0 = *(const u32*)(Blo + nrow * BPAD + kb);
        u32 bl1 = *(const u32*)(Blo + nrow * BPAD + kb + 8);
        mma16816(acc[j][0], acc[j][1], acc[j][2], acc[j][3],
                 ah[0], ah[1], ah[2], ah[3], bh0, bh1);
        mma16816(acc[j][0], acc[j][1], acc[j][2], acc[j][3],
                 ah[0], ah[1], ah[2], ah[3], bl0, bl1);
        mma16816(acc[j][0], acc[j][1], acc[j][2], acc[j][3],
                 al[0], al[1], al[2], al[3], bh0, bh1);
    }
}

// -------------------- K_sgemm: s_proj ---------------------------------------
__global__ void __launch_bounds__(256) k_sgemm(const float* __restrict__ slots,
                                               const float* __restrict__ Wproj,
                                               const float* __restrict__ bproj) {
    __shared__ __align__(16) __nv_bfloat16 Bhi[128 * BPAD];
    __shared__ __align__(16) __nv_bfloat16 Blo[128 * BPAD];

    int tid = threadIdx.x, wid = tid >> 5, lane = tid & 31;
    int m0 = blockIdx.x * 32;
    int mbase = (wid & 1) * 16, n0 = (wid >> 1) * 32;
    const float* arow = slots + (size_t)(m0 + mbase + (lane >> 2)) * D_MODEL
                              + (lane & 3) * 2;
    float acc[4][4];
#pragma unroll
    for (int j = 0; j < 4; j++)
#pragma unroll
        for (int q = 0; q < 4; q++) acc[j][q] = 0.f;

#pragma unroll 1
    for (int kc = 0; kc < 4; kc++) {
        __syncthreads();
        stage_B(Wproj, 256, kc, tid, Bhi, Blo);
        __syncthreads();
#pragma unroll
        for (int ks = 0; ks < 4; ks++)
            mma_step(arow, kc * 64 + ks * 16, Bhi, Blo, n0, lane, acc);
    }

    int r0 = m0 + mbase + (lane >> 2);
#pragma unroll
    for (int j = 0; j < 4; j++) {
        int col = n0 + j * 8 + (lane & 3) * 2;
        float2 bp = *(const float2*)(bproj + col);
        float2 v0; v0.x = acc[j][0] + bp.x; v0.y = acc[j][1] + bp.y;
        float2 v1; v1.x = acc[j][2] + bp.x; v1.y = acc[j][3] + bp.y;
        *(float2*)(g_sproj + (size_t)r0 * D_HID + col) = v0;
        *(float2*)(g_sproj + (size_t)(r0 + 8) * D_HID + col) = v1;
    }
}

// -------------------- K_main: fused f_proj GEMM + relu-dot ------------------
// grid 256: b = blk>>5, t0 = (blk&31)*32.  smem: Bhi|Blo|ssh|wsh, fsh aliases
// Bhi after the mainloop.  2 blocks/SM.
#define FS 132
#define BT_BYTES (128 * BPAD * 2)                    // 18432 per tile
#define SSH_OFF  (2 * BT_BYTES)                      // float region start
#define MAIN_SMEM (2 * BT_BYTES + 64 * FS * 4 + 512) // 71168 B

extern __shared__ char msm[];

__global__ void __launch_bounds__(256) k_main(const float* __restrict__ features,
                                              const float* __restrict__ Wproj,
                                              const float* __restrict__ whead,
                                              const float* __restrict__ bhead,
                                              float* __restrict__ out) {
    __nv_bfloat16* Bhi = (__nv_bfloat16*)msm;
    __nv_bfloat16* Blo = (__nv_bfloat16*)(msm + BT_BYTES);
    float* ssh = (float*)(msm + SSH_OFF);            // 64 x 132
    u64*   wsh = (u64*)(msm + SSH_OFF + 64 * FS * 4);
    float* fsh = (float*)msm;                        // alias: 32 x 132 (16.9KB)

    int tid = threadIdx.x, wid = tid >> 5, lane = tid & 31;
    int b = blockIdx.x >> 5, t0 = (blockIdx.x & 31) * 32;
    int mbase = (wid & 1) * 16, n0 = (wid >> 1) * 32;

    // stage s/w early — latency hides under Phase A
#pragma unroll
    for (int i = 0; i < 8; i++) {
        int q = i * 256 + tid;
        int r = q >> 5, c4 = (q & 31) * 4;
        *(float4*)&ssh[r * FS + c4] =
            *(const float4*)(g_sproj + (size_t)(b * NSLOT + r) * D_HID + c4);
    }
    if (tid < 64) wsh[tid] = ((const u64*)whead)[tid];
    float bh = bhead[0];

    // ---------------- Phase A: HMMA GEMM --------------------------------
    const float* arow = features
        + (size_t)(b * SEQ + t0 + mbase + (lane >> 2)) * D_MODEL + (lane & 3) * 2;
    float acc[4][4];
#pragma unroll
    for (int j = 0; j < 4; j++)
#pragma unroll
        for (int q = 0; q < 4; q++) acc[j][q] = 0.f;

#pragma unroll 1
    for (int kc = 0; kc < 4; kc++) {
        __syncthreads();
        stage_B(Wproj, 0, kc, tid, Bhi, Blo);
        __syncthreads();
#pragma unroll
        for (int ks = 0; ks < 4; ks++)
            mma_step(arow, kc * 64 + ks * 16, Bhi, Blo, n0, lane, acc);
    }
    __syncthreads();                 // B tiles dead; fsh may overwrite

    // acc -> fsh
    int mrow = mbase + (lane >> 2);
#pragma unroll
    for (int j = 0; j < 4; j++) {
        int col = n0 + j * 8 + (lane & 3) * 2;
        float2 v0; v0.x = acc[j][0]; v0.y = acc[j][1];
        float2 v1; v1.x = acc[j][2]; v1.y = acc[j][3];
        *(float2*)&fsh[mrow * FS + col] = v0;
        *(float2*)&fsh[(mrow + 8) * FS + col] = v1;
    }
    __syncthreads();

    // ---------------- Phase B: relu-dot, 4t x 2n ------------------------
    int tq = lane >> 2, np = lane & 3;
    int nn = wid * 8 + np * 2;
    const float* fp = fsh + tq * FS;
    const float* sp = ssh + nn * FS;

    u64 bacc[4][2];
#pragma unroll
    for (int i = 0; i < 4; i++) { bacc[i][0] = 0ULL; bacc[i][1] = 0ULL; }

#pragma unroll 4
    for (int hp = 0; hp < 64; hp++) {
        u64 w2 = wsh[hp];
        u64 s20 = *(const u64*)&sp[2 * hp];
        u64 s21 = *(const u64*)&sp[FS + 2 * hp];
#pragma unroll
        for (int i = 0; i < 4; i++) {
            u64 f2 = *(const u64*)&fp[i * 8 * FS + 2 * hp];
            bacc[i][0] = fma2(relu2(add2(f2, s20)), w2, bacc[i][0]);
            bacc[i][1] = fma2(relu2(add2(f2, s21)), w2, bacc[i][1]);
        }
    }

#pragma unroll
    for (int i = 0; i < 4; i++) {
        int t = tq + 8 * i;
        float a, c, d, e;
        unpack2(bacc[i][0], a, c);
        unpack2(bacc[i][1], d, e);
        float2 o; o.x = a + c + bh; o.y = d + e + bh;
        *(float2*)&out[(size_t)(b * SEQ + t0 + t) * NSLOT + nn] = o;
    }
}

// -------------------- launch -----------------------------------------------
extern "C" void kernel_launch(void* const* d_in, const int* in_sizes, int n_in,
                              void* d_out, int out_size) {
    const float* features = (const float*)d_in[0];
    const float* slots    = (const float*)d_in[1];
    const float* W_proj   = (const float*)d_in[2];
    const float* b_proj   = (const float*)d_in[3];
    const float* w_head   = (const float*)d_in[4];
    const float* b_head   = (const float*)d_in[5];
    float* out = (float*)d_out;

    cudaFuncSetAttribute(k_main, cudaFuncAttributeMaxDynamicSharedMemorySize,
                         MAIN_SMEM);

    k_sgemm<<<16, 256>>>(slots, W_proj, b_proj);
    k_main<<<256, 256, MAIN_SMEM>>>(features, W_proj, w_head, b_head, out);
}

// round 14
// speedup vs baseline: 1.2688x; 1.0906x over previous
#include <cuda_runtime.h>
#include <cuda_bf16.h>
#include <cstdint>

// ---------------------------------------------------------------------------
// ASDHead v10 — pipelined staging + lean Phase B:
//  k_sgemm : s_proj, 64 blocks (n-split 4), HMMA core. ~2us.
//  k_main  : fused f_proj GEMM + relu-dot, grid 256, single wave @2 blk/SM.
//            B staging double-buffered (LDG prefetch under mma);
//            Phase B all-LDS.128 (ulonglong2), f loads shared across n.
// ---------------------------------------------------------------------------

#define D_MODEL 256
#define D_HID   128
#define BATCH   8
#define SEQ     1024
#define NSLOT   64
#define BPAD    72

typedef unsigned long long u64;
typedef unsigned int u32;

__device__ float g_sproj[BATCH * NSLOT * D_HID];   // 256 KB

// -------------------- helpers ----------------------------------------------
__device__ __forceinline__ u64 fma2(u64 a, u64 b, u64 c) {
    u64 d; asm("fma.rn.f32x2 %0, %1, %2, %3;" : "=l"(d) : "l"(a), "l"(b), "l"(c));
    return d;
}
__device__ __forceinline__ u64 add2(u64 a, u64 b) {
    u64 d; asm("add.rn.f32x2 %0, %1, %2;" : "=l"(d) : "l"(a), "l"(b));
    return d;
}
__device__ __forceinline__ void unpack2(u64 v, float& lo, float& hi) {
    asm("mov.b64 {%0, %1}, %2;" : "=f"(lo), "=f"(hi) : "l"(v));
}
__device__ __forceinline__ u64 relu2(u64 x) {
    float lo, hi; unpack2(x, lo, hi);
    lo = fmaxf(lo, 0.f); hi = fmaxf(hi, 0.f);
    u64 r; asm("mov.b64 %0, {%1, %2};" : "=l"(r) : "f"(lo), "f"(hi));
    return r;
}
__device__ __forceinline__ u32 cvt_bf16x2(float a, float b) {
    u32 r; asm("cvt.rn.bf16x2.f32 %0, %1, %2;" : "=r"(r) : "f"(b), "f"(a));
    return r;
}
__device__ __forceinline__ void split2(float x, float y, u32& hi, u32& lo) {
    hi = cvt_bf16x2(x, y);
    float hx = __uint_as_float(hi << 16);
    float hy = __uint_as_float(hi & 0xFFFF0000u);
    lo = cvt_bf16x2(x - hx, y - hy);
}
__device__ __forceinline__ void mma16816(float& c0, float& c1, float& c2, float& c3,
                                         u32 a0, u32 a1, u32 a2, u32 a3,
                                         u32 b0, u32 b1) {
    asm volatile(
        "mma.sync.aligned.m16n8k16.row.col.f32.bf16.bf16.f32 "
        "{%0,%1,%2,%3}, {%4,%5,%6,%7}, {%8,%9}, {%0,%1,%2,%3};"
        : "+f"(c0), "+f"(c1), "+f"(c2), "+f"(c3)
        : "r"(a0), "r"(a1), "r"(a2), "r"(a3), "r"(b0), "r"(b1));
}
// A fragment load + hi/lo split for one 16-k step
__device__ __forceinline__ void load_a(const float* __restrict__ arow, int kk,
                                       u32 ah[4], u32 al[4]) {
    float2 p00 = *(const float2*)(arow + kk);
    float2 p10 = *(const float2*)(arow + kk + 8 * D_MODEL);
    float2 p01 = *(const float2*)(arow + kk + 8);
    float2 p11 = *(const float2*)(arow + kk + 8 * D_MODEL + 8);
    split2(p00.x, p00.y, ah[0], al[0]);
    split2(p10.x, p10.y, ah[1], al[1]);
    split2(p01.x, p01.y, ah[2], al[2]);
    split2(p11.x, p11.y, ah[3], al[3]);
}

// -------------------- K_sgemm: s_proj, 64 blocks ----------------------------
// blk: m0 = (blk>>2)*32, nbase = (blk&3)*32.  warp: 16m x 8n tile.
__global__ void __launch_bounds__(256) k_sgemm(const float* __restrict__ slots,
                                               const float* __restrict__ Wproj,
                                               const float* __restrict__ bproj) {
    __shared__ __align__(16) __nv_bfloat16 Bhi[32 * BPAD];
    __shared__ __align__(16) __nv_bfloat16 Blo[32 * BPAD];

    int tid = threadIdx.x, wid = tid >> 5, lane = tid & 31;
    int m0 = (blockIdx.x >> 2) * 32, nbase = (blockIdx.x & 3) * 32;
    int mbase = (wid & 1) * 16, ng = wid >> 1;

    const float* arow = slots + (size_t)(m0 + mbase + (lane >> 2)) * D_MODEL
                              + (lane & 3) * 2;
    float acc[4] = {0.f, 0.f, 0.f, 0.f};

#pragma unroll 1
    for (int kc = 0; kc < 4; kc++) {
        __syncthreads();
        {   // stage 32 h-rows x 64 k: h = tid&31, kg = tid>>5 (8 k each)
            int h = tid & 31, kg = tid >> 5;
            const float* wp = Wproj
                + (size_t)(256 + kc * 64 + kg * 8) * D_HID + nbase + h;
            u32 hb[4], lb[4];
#pragma unroll
            for (int p = 0; p < 4; p++) {
                float x0 = wp[(2 * p) * D_HID];
                float x1 = wp[(2 * p + 1) * D_HID];
                split2(x0, x1, hb[p], lb[p]);
            }
            *(uint4*)(Bhi + h * BPAD + kg * 8) = make_uint4(hb[0], hb[1], hb[2], hb[3]);
            *(uint4*)(Blo + h * BPAD + kg * 8) = make_uint4(lb[0], lb[1], lb[2], lb[3]);
        }
        __syncthreads();

#pragma unroll
        for (int ks = 0; ks < 4; ks++) {
            u32 ah[4], al[4];
            load_a(arow, kc * 64 + ks * 16, ah, al);
            int nrow = ng * 8 + (lane >> 2);
            int kb = ks * 16 + (lane & 3) * 2;
            u32 bh0 = *(const u32*)(Bhi + nrow * BPAD + kb);
            u32 bh1 = *(const u32*)(Bhi + nrow * BPAD + kb + 8);
            u32 bl0 = *(const u32*)(Blo + nrow * BPAD + kb);
            u32 bl1 = *(const u32*)(Blo + nrow * BPAD + kb + 8);
            mma16816(acc[0], acc[1], acc[2], acc[3], ah[0], ah[1], ah[2], ah[3], bh0, bh1);
            mma16816(acc[0], acc[1], acc[2], acc[3], ah[0], ah[1], ah[2], ah[3], bl0, bl1);
            mma16816(acc[0], acc[1], acc[2], acc[3], al[0], al[1], al[2], al[3], bh0, bh1);
        }
    }

    int r0 = m0 + mbase + (lane >> 2);
    int col = nbase + ng * 8 + (lane & 3) * 2;
    float2 bp = *(const float2*)(bproj + col);
    float2 v0; v0.x = acc[0] + bp.x; v0.y = acc[1] + bp.y;
    float2 v1; v1.x = acc[2] + bp.x; v1.y = acc[3] + bp.y;
    *(float2*)(g_sproj + (size_t)r0 * D_HID + col) = v0;
    *(float2*)(g_sproj + (size_t)(r0 + 8) * D_HID + col) = v1;
}

// -------------------- K_main: fused GEMM + relu-dot -------------------------
// grid 256: b = blk>>5, t0 = (blk&31)*32.  Double-buffered B; fsh aliases buf0.
#define FS 132
#define BT  18432                         // one B tile (hi or lo) bytes
#define SSH_OFF (4 * BT)                  // 73728
#define WSH_OFF (SSH_OFF + 64 * FS * 4)   // 107520
#define MAIN_SMEM (WSH_OFF + 512)         // 108032

extern __shared__ char msm[];

__global__ void __launch_bounds__(256, 2) k_main(const float* __restrict__ features,
                                                 const float* __restrict__ Wproj,
                                                 const float* __restrict__ whead,
                                                 const float* __restrict__ bhead,
                                                 float* __restrict__ out) {
    __nv_bfloat16* Bh[2] = { (__nv_bfloat16*)msm,            (__nv_bfloat16*)(msm + 2 * BT) };
    __nv_bfloat16* Bl[2] = { (__nv_bfloat16*)(msm + BT),     (__nv_bfloat16*)(msm + 3 * BT) };
    float* ssh = (float*)(msm + SSH_OFF);          // 64 x 132
    u64*   wsh = (u64*)(msm + WSH_OFF);
    float* fsh = (float*)msm;                      // alias buf0 (16.9KB < 18.4KB)

    int tid = threadIdx.x, wid = tid >> 5, lane = tid & 31;
    int b = blockIdx.x >> 5, t0 = (blockIdx.x & 31) * 32;
    int mbase = (wid & 1) * 16, n0 = (wid >> 1) * 32;
    int h = tid & 127, kg = tid >> 7;              // staging ownership

    // stage s/w early — LDG latency hides under Phase A
#pragma unroll
    for (int i = 0; i < 8; i++) {
        int q = i * 256 + tid;
        int r = q >> 5, c4 = (q & 31) * 4;
        *(float4*)&ssh[r * FS + c4] =
            *(const float4*)(g_sproj + (size_t)(b * NSLOT + r) * D_HID + c4);
    }
    if (tid < 64) wsh[tid] = ((const u64*)whead)[tid];
    float bh = bhead[0];

    const float* arow = features
        + (size_t)(b * SEQ + t0 + mbase + (lane >> 2)) * D_MODEL + (lane & 3) * 2;
    float acc[4][4];
#pragma unroll
    for (int j = 0; j < 4; j++)
#pragma unroll
        for (int q = 0; q < 4; q++) acc[j][q] = 0.f;

    float ar[32];                                  // B prefetch registers
    // prologue: load + store chunk 0
    {
        const float* wp = Wproj + (size_t)(kg * 32) * D_HID + h;
#pragma unroll
        for (int i = 0; i < 32; i++) ar[i] = wp[i * D_HID];
#pragma unroll
        for (int grp = 0; grp < 4; grp++) {
            u32 hb[4], lb[4];
#pragma unroll
            for (int p = 0; p < 4; p++)
                split2(ar[grp * 8 + 2 * p], ar[grp * 8 + 2 * p + 1], hb[p], lb[p]);
            *(uint4*)(Bh[0] + h * BPAD + kg * 32 + grp * 8) =
                make_uint4(hb[0], hb[1], hb[2], hb[3]);
            *(uint4*)(Bl[0] + h * BPAD + kg * 32 + grp * 8) =
                make_uint4(lb[0], lb[1], lb[2], lb[3]);
        }
    }
    __syncthreads();

#pragma unroll 1
    for (int kc = 0; kc < 4; kc++) {
        if (kc < 3) {                              // prefetch next chunk (LDG only)
            const float* wp = Wproj + (size_t)((kc + 1) * 64 + kg * 32) * D_HID + h;
#pragma unroll
            for (int i = 0; i < 32; i++) ar[i] = wp[i * D_HID];
        }
        const __nv_bfloat16* bhc = Bh[kc & 1];
        const __nv_bfloat16* blc = Bl[kc & 1];
#pragma unroll
        for (int ks = 0; ks < 4; ks++) {           // mma overlaps prefetch latency
            u32 ah[4], al[4];
            load_a(arow, kc * 64 + ks * 16, ah, al);
            int kb = ks * 16 + (lane & 3) * 2;
#pragma unroll
            for (int j = 0; j < 4; j++) {
                int nrow = n0 + j * 8 + (lane >> 2);
                u32 bh0 = *(const u32*)(bhc + nrow * BPAD + kb);
                u32 bh1 = *(const u32*)(bhc + nrow * BPAD + kb + 8);
                u32 bl0 = *(const u32*)(blc + nrow * BPAD + kb);
                u32 bl1 = *(const u32*)(blc + nrow * BPAD + kb + 8);
                mma16816(acc[j][0], acc[j][1], acc[j][2], acc[j][3],
                         ah[0], ah[1], ah[2], ah[3], bh0, bh1);
                mma16816(acc[j][0], acc[j][1], acc[j][2], acc[j][3],
                         ah[0], ah[1], ah[2], ah[3], bl0, bl1);
                mma16816(acc[j][0], acc[j][1], acc[j][2], acc[j][3],
                         al[0], al[1], al[2], al[3], bh0, bh1);
            }
        }
        if (kc < 3) {                              // split + store into other buffer
            __nv_bfloat16* bhn = Bh[(kc + 1) & 1];
            __nv_bfloat16* bln = Bl[(kc + 1) & 1];
#pragma unroll
            for (int grp = 0; grp < 4; grp++) {
                u32 hb[4], lb[4];
#pragma unroll
                for (int p = 0; p < 4; p++)
                    split2(ar[grp * 8 + 2 * p], ar[grp * 8 + 2 * p + 1], hb[p], lb[p]);
                *(uint4*)(bhn + h * BPAD + kg * 32 + grp * 8) =
                    make_uint4(hb[0], hb[1], hb[2], hb[3]);
                *(uint4*)(bln + h * BPAD + kg * 32 + grp * 8) =
                    make_uint4(lb[0], lb[1], lb[2], lb[3]);
            }
            __syncthreads();
        }
    }
    __syncthreads();                               // all mma done; buf0 reusable

    // acc -> fsh
    int mrow = mbase + (lane >> 2);
#pragma unroll
    for (int j = 0; j < 4; j++) {
        int col = n0 + j * 8 + (lane & 3) * 2;
        float2 v0; v0.x = acc[j][0]; v0.y = acc[j][1];
        float2 v1; v1.x = acc[j][2]; v1.y = acc[j][3];
        *(float2*)&fsh[mrow * FS + col] = v0;
        *(float2*)&fsh[(mrow + 8) * FS + col] = v1;
    }
    __syncthreads();

    // ---------------- Phase B: relu-dot, 4t x 2n, all LDS.128 ------------
    int tq = lane >> 2, np = lane & 3;
    int nn = wid * 8 + np * 2;
    const float* fp = fsh + tq * FS;
    const float* sp = ssh + nn * FS;

    u64 bacc[4][2];
#pragma unroll
    for (int i = 0; i < 4; i++) { bacc[i][0] = 0ULL; bacc[i][1] = 0ULL; }

#pragma unroll 4
    for (int h2 = 0; h2 < 32; h2++) {              // 2 h-pairs per iter
        ulonglong2 wv  = *(const ulonglong2*)&wsh[2 * h2];
        ulonglong2 sv0 = *(const ulonglong2*)&sp[4 * h2];
        ulonglong2 sv1 = *(const ulonglong2*)&sp[FS + 4 * h2];
#pragma unroll
        for (int i = 0; i < 4; i++) {
            ulonglong2 fv = *(const ulonglong2*)&fp[i * 8 * FS + 4 * h2];
            bacc[i][0] = fma2(relu2(add2(fv.x, sv0.x)), wv.x, bacc[i][0]);
            bacc[i][0] = fma2(relu2(add2(fv.y, sv0.y)), wv.y, bacc[i][0]);
            bacc[i][1] = fma2(relu2(add2(fv.x, sv1.x)), wv.x, bacc[i][1]);
            bacc[i][1] = fma2(relu2(add2(fv.y, sv1.y)), wv.y, bacc[i][1]);
        }
    }

#pragma unroll
    for (int i = 0; i < 4; i++) {
        int t = tq + 8 * i;
        float a, c, d, e;
        unpack2(bacc[i][0], a, c);
        unpack2(bacc[i][1], d, e);
        float2 o; o.x = a + c + bh; o.y = d + e + bh;
        *(float2*)&out[(size_t)(b * SEQ + t0 + t) * NSLOT + nn] = o;
    }
}

// -------------------- launch -----------------------------------------------
extern "C" void kernel_launch(void* const* d_in, const int* in_sizes, int n_in,
                              void* d_out, int out_size) {
    const float* features = (const float*)d_in[0];
    const float* slots    = (const float*)d_in[1];
    const float* W_proj   = (const float*)d_in[2];
    const float* b_proj   = (const float*)d_in[3];
    const float* w_head   = (const float*)d_in[4];
    const float* b_head   = (const float*)d_in[5];
    float* out = (float*)d_out;

    cudaFuncSetAttribute(k_main, cudaFuncAttributeMaxDynamicSharedMemorySize,
                         MAIN_SMEM);

    k_sgemm<<<64, 256>>>(slots, W_proj, b_proj);
    k_main<<<256, 256, MAIN_SMEM>>>(features, W_proj, w_head, b_head, out);
}